// round 11
// baseline (speedup 1.0000x reference)
#include <cuda_runtime.h>
#include <cuda_fp16.h>

#define NSEQ 1024
#define CH   64
#define NPTS (2 * NSEQ)

// Scratch (allocation-free rule: __device__ globals). fp16 projections.
__device__ __align__(16) __half g_Hi[NPTS * CH];  //  y + b1   (i side)
__device__ __align__(16) __half g_Hj[NPTS * CH];  // -y        (j side, pre-negated)

static __device__ __forceinline__ __half2 u2h(unsigned u) {
    return *reinterpret_cast<const __half2*>(&u);
}
static __device__ __forceinline__ unsigned h2u(__half2 h) {
    return *reinterpret_cast<const unsigned*>(&h);
}

// ---------------------------------------------------------------------------
// K1: y[p][o] = sum_c W1[o][c] * x[p][c];  Hi = half(y+b1); Hj = half(-y)
// 256 blocks x 8 points, 256 threads (o = t&63, pg = t>>6 -> 2 points each).
// ---------------------------------------------------------------------------
__global__ void k1_proj(const float* __restrict__ x,
                        const float* __restrict__ w1,
                        const float* __restrict__ b1) {
    __shared__ float W1T[CH][65];                  // [c][o]
    __shared__ __align__(16) float xsT[CH][12];    // [c][p], 48B rows
    __shared__ float b1s[CH];

    int t = threadIdx.x;
    int p0 = blockIdx.x * 8;

#pragma unroll
    for (int q = t; q < 1024; q += 256) {
        int o = q >> 4, c4 = (q & 15) * 4;
        float4 v = reinterpret_cast<const float4*>(w1)[q];
        W1T[c4 + 0][o] = v.x;
        W1T[c4 + 1][o] = v.y;
        W1T[c4 + 2][o] = v.z;
        W1T[c4 + 3][o] = v.w;
    }
    if (t < 128) {   // 8 points x 64 ch = 128 float4
        int pl = t >> 4, c4 = (t & 15) * 4;
        float4 v = reinterpret_cast<const float4*>(x + p0 * CH)[t];
        xsT[c4 + 0][pl] = v.x;
        xsT[c4 + 1][pl] = v.y;
        xsT[c4 + 2][pl] = v.z;
        xsT[c4 + 3][pl] = v.w;
    }
    if (t < CH) b1s[t] = b1[t];
    __syncthreads();

    int o = t & 63, pg = t >> 6;   // pg 0..3 -> points 2pg, 2pg+1
    float a0 = 0.f, a1 = 0.f;
#pragma unroll
    for (int c = 0; c < CH; ++c) {
        float wv = W1T[c][o];
        float2 xv = *reinterpret_cast<const float2*>(&xsT[c][pg * 2]);
        a0 += wv * xv.x;
        a1 += wv * xv.y;
    }

    float b1v = b1s[o];
    int pbase = p0 + pg * 2;
    g_Hj[(pbase + 0) * CH + o] = __float2half_rn(-a0);
    g_Hi[(pbase + 0) * CH + o] = __float2half_rn(a0 + b1v);
    g_Hj[(pbase + 1) * CH + o] = __float2half_rn(-a1);
    g_Hi[(pbase + 1) * CH + o] = __float2half_rn(a1 + b1v);
}

// ---------------------------------------------------------------------------
// K2: raw scores, fp16 packed pair math. Tile 64 i x 128 j (64 j-pairs),
// 256 threads, microtile 4i x 4jp (8 j) per thread. fp16 accumulators dumped
// to fp32 every 16 channels. rI/rJn dots run concurrently with the main loop
// (consumed only in the epilogue, after the single post-main barrier).
// Grid: (jt=8, it=16, b=2) = 256 blocks (all resident in one wave).
// ---------------------------------------------------------------------------
__global__ void __launch_bounds__(256, 2)
k2_scores(const float* __restrict__ w2,
          const float* __restrict__ b2p,
          float* __restrict__ out) {
    __shared__ __align__(16) unsigned His[64][66];   // dup'd (yi,yi)
    __shared__ __align__(16) unsigned Hjs[64][66];   // paired (yj0,yj1)
    __shared__ __align__(16) unsigned wdup[CH];      // dup'd (w2h,w2h)
    __shared__ float w2hs[CH];
    __shared__ float rIs[64], rJn[128];

    int t  = threadIdx.x;
    int jt = blockIdx.x, it = blockIdx.y, b = blockIdx.z;
    size_t bb = (size_t)b * NSEQ * CH;

    // --- stage His (dup): thread -> row t>>2, 16 channels ---
    {
        int row = t >> 2, c16 = (t & 3) * 16;
        const uint4* src = reinterpret_cast<const uint4*>(
            g_Hi + bb + (size_t)(it * 64 + row) * CH + c16);
        uint4 u0 = src[0], u1 = src[1];
        unsigned wsrc[8] = {u0.x, u0.y, u0.z, u0.w, u1.x, u1.y, u1.z, u1.w};
#pragma unroll
        for (int k = 0; k < 8; ++k) {
            His[row][c16 + 2 * k]     = __byte_perm(wsrc[k], 0, 0x1010);
            His[row][c16 + 2 * k + 1] = __byte_perm(wsrc[k], 0, 0x3232);
        }
    }
    // --- stage Hjs (j-pairs): thread -> jp = t>>2, 16 channels ---
    {
        int jp = t >> 2, c16 = (t & 3) * 16;
        const uint4* pa = reinterpret_cast<const uint4*>(
            g_Hj + bb + (size_t)(jt * 128 + 2 * jp) * CH + c16);
        const uint4* pb = reinterpret_cast<const uint4*>(
            g_Hj + bb + (size_t)(jt * 128 + 2 * jp + 1) * CH + c16);
        uint4 A0 = pa[0], A1 = pa[1];
        uint4 B0 = pb[0], B1 = pb[1];
        unsigned av[8] = {A0.x, A0.y, A0.z, A0.w, A1.x, A1.y, A1.z, A1.w};
        unsigned bv[8] = {B0.x, B0.y, B0.z, B0.w, B1.x, B1.y, B1.z, B1.w};
#pragma unroll
        for (int k = 0; k < 8; ++k) {
            Hjs[jp][c16 + 2 * k]     = __byte_perm(av[k], bv[k], 0x5410);
            Hjs[jp][c16 + 2 * k + 1] = __byte_perm(av[k], bv[k], 0x7632);
        }
    }
    if (t < CH) {
        float wh = 0.5f * w2[t];
        w2hs[t] = wh;
        wdup[t] = h2u(__half2half2(__float2half_rn(wh)));
    }
    __syncthreads();

    // --- per-row scalars (fp32, ILP-4), overlapped with the main loop ---
    // Written to rIs/rJn here; consumed only after the post-main barrier.
    if (t < 64) {
        const __half2* row = reinterpret_cast<const __half2*>(&His[t][0]);
        float a0 = 0.f, a1 = 0.f, a2 = 0.f, a3 = 0.f;
#pragma unroll
        for (int c = 0; c < CH; c += 4) {
            a0 += w2hs[c + 0] * __low2float(row[c + 0]);
            a1 += w2hs[c + 1] * __low2float(row[c + 1]);
            a2 += w2hs[c + 2] * __low2float(row[c + 2]);
            a3 += w2hs[c + 3] * __low2float(row[c + 3]);
        }
        rIs[t] = (a0 + a1) + (a2 + a3) + b2p[0];
    } else if (t < 192) {
        int j = t - 64, jp = j >> 1;
        const __half2* row = reinterpret_cast<const __half2*>(&Hjs[jp][0]);
        float a0 = 0.f, a1 = 0.f, a2 = 0.f, a3 = 0.f;
        if (j & 1) {
#pragma unroll
            for (int c = 0; c < CH; c += 4) {
                a0 += w2hs[c + 0] * __high2float(row[c + 0]);
                a1 += w2hs[c + 1] * __high2float(row[c + 1]);
                a2 += w2hs[c + 2] * __high2float(row[c + 2]);
                a3 += w2hs[c + 3] * __high2float(row[c + 3]);
            }
        } else {
#pragma unroll
            for (int c = 0; c < CH; c += 4) {
                a0 += w2hs[c + 0] * __low2float(row[c + 0]);
                a1 += w2hs[c + 1] * __low2float(row[c + 1]);
                a2 += w2hs[c + 2] * __low2float(row[c + 2]);
                a3 += w2hs[c + 3] * __low2float(row[c + 3]);
            }
        }
        rJn[j] = (a0 + a1) + (a2 + a3);
    }

    int tx = t & 15, ty = t >> 4;   // i = ty+16r; jp = tx+16s (j = 2jp, 2jp+1)
    float accf[4][4][2] = {};

#pragma unroll
    for (int cd = 0; cd < 4; ++cd) {
        __half2 acc[4][4];
#pragma unroll
        for (int r = 0; r < 4; ++r)
#pragma unroll
            for (int s = 0; s < 4; ++s) acc[r][s] = __float2half2_rn(0.f);

#pragma unroll
        for (int c8 = 0; c8 < 8; ++c8) {
            int c = cd * 16 + c8 * 2;
            uint2 wv = *reinterpret_cast<const uint2*>(&wdup[c]);
            __half2 wA = u2h(wv.x), wB = u2h(wv.y);
            uint2 yi[4], zj[4];
#pragma unroll
            for (int r = 0; r < 4; ++r)
                yi[r] = *reinterpret_cast<const uint2*>(&His[ty + 16 * r][c]);
#pragma unroll
            for (int s = 0; s < 4; ++s)
                zj[s] = *reinterpret_cast<const uint2*>(&Hjs[tx + 16 * s][c]);
#pragma unroll
            for (int r = 0; r < 4; ++r)
#pragma unroll
                for (int s = 0; s < 4; ++s) {
                    __half2 dA = __habs2(__hadd2(u2h(yi[r].x), u2h(zj[s].x)));
                    acc[r][s] = __hfma2(wA, dA, acc[r][s]);
                    __half2 dB = __habs2(__hadd2(u2h(yi[r].y), u2h(zj[s].y)));
                    acc[r][s] = __hfma2(wB, dB, acc[r][s]);
                }
        }
#pragma unroll
        for (int r = 0; r < 4; ++r)
#pragma unroll
            for (int s = 0; s < 4; ++s) {
                float2 f = __half22float2(acc[r][s]);
                accf[r][s][0] += f.x;
                accf[r][s][1] += f.y;
            }
    }

    __syncthreads();   // rIs/rJn now final

#pragma unroll
    for (int r = 0; r < 4; ++r) {
        int il = ty + 16 * r;
        float ri = rIs[il];
        float* orow = out + ((size_t)(b * NSEQ + it * 64 + il)) * NSEQ + jt * 128;
#pragma unroll
        for (int s = 0; s < 4; ++s) {
            int j0 = 2 * (tx + 16 * s);
            float2 v;
            v.x = ri + rJn[j0]     + accf[r][s][0];
            v.y = ri + rJn[j0 + 1] + accf[r][s][1];
            *reinterpret_cast<float2*>(&orow[j0]) = v;
        }
    }
}

// ---------------------------------------------------------------------------
// K3: in-place row softmax over j. One block per (b,i) row. 256 threads,
// float4 vectorized.
// ---------------------------------------------------------------------------
__global__ void k3_softmax(float* __restrict__ out) {
    __shared__ float red[8];
    __shared__ float bcast;
    size_t base = (size_t)blockIdx.x * NSEQ;
    int t = threadIdx.x;

    float4 v = reinterpret_cast<const float4*>(out + base)[t];

    float m = fmaxf(fmaxf(v.x, v.y), fmaxf(v.z, v.w));
#pragma unroll
    for (int o = 16; o; o >>= 1) m = fmaxf(m, __shfl_xor_sync(0xffffffffu, m, o));
    if ((t & 31) == 0) red[t >> 5] = m;
    __syncthreads();
    if (t == 0) {
        float mm = red[0];
#pragma unroll
        for (int i = 1; i < 8; ++i) mm = fmaxf(mm, red[i]);
        bcast = mm;
    }
    __syncthreads();
    m = bcast;

    float4 e;
    e.x = __expf(v.x - m);
    e.y = __expf(v.y - m);
    e.z = __expf(v.z - m);
    e.w = __expf(v.w - m);
    float s = (e.x + e.y) + (e.z + e.w);
#pragma unroll
    for (int o = 16; o; o >>= 1) s += __shfl_xor_sync(0xffffffffu, s, o);
    __syncthreads();
    if ((t & 31) == 0) red[t >> 5] = s;
    __syncthreads();
    if (t == 0) {
        float ss = red[0];
#pragma unroll
        for (int i = 1; i < 8; ++i) ss += red[i];
        bcast = 1.0f / ss;
    }
    __syncthreads();
    float inv = bcast;

    e.x *= inv;  e.y *= inv;  e.z *= inv;  e.w *= inv;
    reinterpret_cast<float4*>(out + base)[t] = e;
}

// ---------------------------------------------------------------------------
extern "C" void kernel_launch(void* const* d_in, const int* in_sizes, int n_in,
                              void* d_out, int out_size) {
    const float* x  = (const float*)d_in[0];  // [2,1024,64]
    const float* w1 = (const float*)d_in[1];  // [64,64]
    const float* b1 = (const float*)d_in[2];  // [64]
    const float* w2 = (const float*)d_in[3];  // [64]
    const float* b2 = (const float*)d_in[4];  // scalar
    float* out = (float*)d_out;               // [2,1024,1024]

    k1_proj<<<256, 256>>>(x, w1, b1);
    dim3 g2(8, 16, 2);
    k2_scores<<<g2, 256>>>(w2, b2, out);
    k3_softmax<<<2048, 256>>>(out);
}

// round 12
// speedup vs baseline: 1.0692x; 1.0692x over previous
#include <cuda_runtime.h>
#include <cuda_fp16.h>

#define NSEQ 1024
#define CH   64
#define NPTS (2 * NSEQ)

// Scratch (allocation-free rule: __device__ globals). fp16 projections.
__device__ __align__(16) __half g_Hi[NPTS * CH];  //  y + b1   (i side)
__device__ __align__(16) __half g_Hj[NPTS * CH];  // -y        (j side, pre-negated)
__device__ float g_rowsum[NPTS];                  // per-(b,i) sum of exp(s)
__device__ unsigned g_cnt[32];                    // per-(b,it) arrival counters

static __device__ __forceinline__ __half2 u2h(unsigned u) {
    return *reinterpret_cast<const __half2*>(&u);
}
static __device__ __forceinline__ unsigned h2u(__half2 h) {
    return *reinterpret_cast<const unsigned*>(&h);
}

// ---------------------------------------------------------------------------
// K1: y[p][o] = sum_c W1[o][c] * x[p][c];  Hi = half(y+b1); Hj = half(-y)
// 128 blocks x 16 points, 256 threads (proven champion shape).
// Also zeroes g_rowsum / g_cnt for this call (graph-replay determinism).
// ---------------------------------------------------------------------------
__global__ void k1_proj(const float* __restrict__ x,
                        const float* __restrict__ w1,
                        const float* __restrict__ b1) {
    __shared__ float W1T[CH][65];                  // [c][o]
    __shared__ __align__(16) float xsT[CH][20];    // [c][p]
    __shared__ float b1s[CH];

    int t = threadIdx.x;
    int p0 = blockIdx.x * 16;

    // zero reduction scratch (blocks 0-7 cover 2048 floats; block 8 the counters)
    if (blockIdx.x < 8)  g_rowsum[blockIdx.x * 256 + t] = 0.f;
    if (blockIdx.x == 8 && t < 32) g_cnt[t] = 0u;

#pragma unroll
    for (int q = t; q < 1024; q += 256) {
        int o = q >> 4, c4 = (q & 15) * 4;
        float4 v = reinterpret_cast<const float4*>(w1)[q];
        W1T[c4 + 0][o] = v.x;
        W1T[c4 + 1][o] = v.y;
        W1T[c4 + 2][o] = v.z;
        W1T[c4 + 3][o] = v.w;
    }
    {
        int pl = t >> 4, c4 = (t & 15) * 4;
        float4 v = reinterpret_cast<const float4*>(x + p0 * CH)[t];
        xsT[c4 + 0][pl] = v.x;
        xsT[c4 + 1][pl] = v.y;
        xsT[c4 + 2][pl] = v.z;
        xsT[c4 + 3][pl] = v.w;
    }
    if (t < CH) b1s[t] = b1[t];
    __syncthreads();

    int o = t & 63, pg = t >> 6;
    float a0 = 0.f, a1 = 0.f, a2 = 0.f, a3 = 0.f;
#pragma unroll
    for (int c = 0; c < CH; ++c) {
        float wv = W1T[c][o];
        float4 xv = *reinterpret_cast<const float4*>(&xsT[c][pg * 4]);
        a0 += wv * xv.x;
        a1 += wv * xv.y;
        a2 += wv * xv.z;
        a3 += wv * xv.w;
    }

    float b1v = b1s[o];
    int pbase = p0 + pg * 4;
    g_Hj[(pbase + 0) * CH + o] = __float2half_rn(-a0);
    g_Hi[(pbase + 0) * CH + o] = __float2half_rn(a0 + b1v);
    g_Hj[(pbase + 1) * CH + o] = __float2half_rn(-a1);
    g_Hi[(pbase + 1) * CH + o] = __float2half_rn(a1 + b1v);
    g_Hj[(pbase + 2) * CH + o] = __float2half_rn(-a2);
    g_Hi[(pbase + 2) * CH + o] = __float2half_rn(a2 + b1v);
    g_Hj[(pbase + 3) * CH + o] = __float2half_rn(-a3);
    g_Hi[(pbase + 3) * CH + o] = __float2half_rn(a3 + b1v);
}

// ---------------------------------------------------------------------------
// K2: scores + fused softmax, one output write.
// Tile 64 i x 128 j, 256 threads, microtile 4i x 4jp. exp(s) without max
// subtraction (scores bounded); cross-block row sums via atomics + counter
// rendezvous (all 256 blocks co-resident: 2/SM). Grid: (jt=8, it=16, b=2).
// ---------------------------------------------------------------------------
__global__ void __launch_bounds__(256, 2)
k2_scores(const float* __restrict__ w2,
          const float* __restrict__ b2p,
          float* __restrict__ out) {
    __shared__ __align__(16) unsigned His[64][66];   // dup'd (yi,yi)
    __shared__ __align__(16) unsigned Hjs[64][66];   // paired (yj0,yj1)
    __shared__ __align__(16) unsigned wdup[CH];      // dup'd (w2h,w2h)
    __shared__ float w2hs[CH];
    __shared__ float rIs[64], rJn[128];
    __shared__ float rsum[64];

    int t  = threadIdx.x;
    int jt = blockIdx.x, it = blockIdx.y, b = blockIdx.z;
    size_t bb = (size_t)b * NSEQ * CH;

    // --- stage His (dup): thread -> row t>>2, 16 channels ---
    {
        int row = t >> 2, c16 = (t & 3) * 16;
        const uint4* src = reinterpret_cast<const uint4*>(
            g_Hi + bb + (size_t)(it * 64 + row) * CH + c16);
        uint4 u0 = src[0], u1 = src[1];
        unsigned wsrc[8] = {u0.x, u0.y, u0.z, u0.w, u1.x, u1.y, u1.z, u1.w};
#pragma unroll
        for (int k = 0; k < 8; ++k) {
            His[row][c16 + 2 * k]     = __byte_perm(wsrc[k], 0, 0x1010);
            His[row][c16 + 2 * k + 1] = __byte_perm(wsrc[k], 0, 0x3232);
        }
    }
    // --- stage Hjs (j-pairs): thread -> jp = t>>2, 16 channels ---
    {
        int jp = t >> 2, c16 = (t & 3) * 16;
        const uint4* pa = reinterpret_cast<const uint4*>(
            g_Hj + bb + (size_t)(jt * 128 + 2 * jp) * CH + c16);
        const uint4* pb = reinterpret_cast<const uint4*>(
            g_Hj + bb + (size_t)(jt * 128 + 2 * jp + 1) * CH + c16);
        uint4 A0 = pa[0], A1 = pa[1];
        uint4 B0 = pb[0], B1 = pb[1];
        unsigned av[8] = {A0.x, A0.y, A0.z, A0.w, A1.x, A1.y, A1.z, A1.w};
        unsigned bv[8] = {B0.x, B0.y, B0.z, B0.w, B1.x, B1.y, B1.z, B1.w};
#pragma unroll
        for (int k = 0; k < 8; ++k) {
            Hjs[jp][c16 + 2 * k]     = __byte_perm(av[k], bv[k], 0x5410);
            Hjs[jp][c16 + 2 * k + 1] = __byte_perm(av[k], bv[k], 0x7632);
        }
    }
    if (t < CH) {
        float wh = 0.5f * w2[t];
        w2hs[t] = wh;
        wdup[t] = h2u(__half2half2(__float2half_rn(wh)));
    }
    __syncthreads();

    // --- per-row scalars (fp32, ILP-4), overlapped with the main loop ---
    if (t < 64) {
        const __half2* row = reinterpret_cast<const __half2*>(&His[t][0]);
        float a0 = 0.f, a1 = 0.f, a2 = 0.f, a3 = 0.f;
#pragma unroll
        for (int c = 0; c < CH; c += 4) {
            a0 += w2hs[c + 0] * __low2float(row[c + 0]);
            a1 += w2hs[c + 1] * __low2float(row[c + 1]);
            a2 += w2hs[c + 2] * __low2float(row[c + 2]);
            a3 += w2hs[c + 3] * __low2float(row[c + 3]);
        }
        rIs[t] = (a0 + a1) + (a2 + a3) + b2p[0];
    } else if (t < 192) {
        int j = t - 64, jp = j >> 1;
        const __half2* row = reinterpret_cast<const __half2*>(&Hjs[jp][0]);
        float a0 = 0.f, a1 = 0.f, a2 = 0.f, a3 = 0.f;
        if (j & 1) {
#pragma unroll
            for (int c = 0; c < CH; c += 4) {
                a0 += w2hs[c + 0] * __high2float(row[c + 0]);
                a1 += w2hs[c + 1] * __high2float(row[c + 1]);
                a2 += w2hs[c + 2] * __high2float(row[c + 2]);
                a3 += w2hs[c + 3] * __high2float(row[c + 3]);
            }
        } else {
#pragma unroll
            for (int c = 0; c < CH; c += 4) {
                a0 += w2hs[c + 0] * __low2float(row[c + 0]);
                a1 += w2hs[c + 1] * __low2float(row[c + 1]);
                a2 += w2hs[c + 2] * __low2float(row[c + 2]);
                a3 += w2hs[c + 3] * __low2float(row[c + 3]);
            }
        }
        rJn[j] = (a0 + a1) + (a2 + a3);
    }

    int tx = t & 15, ty = t >> 4;   // i = ty+16r; jp = tx+16s (j = 2jp, 2jp+1)
    float accf[4][4][2] = {};

#pragma unroll
    for (int cd = 0; cd < 4; ++cd) {
        __half2 acc[4][4];
#pragma unroll
        for (int r = 0; r < 4; ++r)
#pragma unroll
            for (int s = 0; s < 4; ++s) acc[r][s] = __float2half2_rn(0.f);

#pragma unroll
        for (int c8 = 0; c8 < 8; ++c8) {
            int c = cd * 16 + c8 * 2;
            uint2 wv = *reinterpret_cast<const uint2*>(&wdup[c]);
            __half2 wA = u2h(wv.x), wB = u2h(wv.y);
            uint2 yi[4], zj[4];
#pragma unroll
            for (int r = 0; r < 4; ++r)
                yi[r] = *reinterpret_cast<const uint2*>(&His[ty + 16 * r][c]);
#pragma unroll
            for (int s = 0; s < 4; ++s)
                zj[s] = *reinterpret_cast<const uint2*>(&Hjs[tx + 16 * s][c]);
#pragma unroll
            for (int r = 0; r < 4; ++r)
#pragma unroll
                for (int s = 0; s < 4; ++s) {
                    __half2 dA = __habs2(__hadd2(u2h(yi[r].x), u2h(zj[s].x)));
                    acc[r][s] = __hfma2(wA, dA, acc[r][s]);
                    __half2 dB = __habs2(__hadd2(u2h(yi[r].y), u2h(zj[s].y)));
                    acc[r][s] = __hfma2(wB, dB, acc[r][s]);
                }
        }
#pragma unroll
        for (int r = 0; r < 4; ++r)
#pragma unroll
            for (int s = 0; s < 4; ++s) {
                float2 f = __half22float2(acc[r][s]);
                accf[r][s][0] += f.x;
                accf[r][s][1] += f.y;
            }
    }

    __syncthreads();   // rIs/rJn final

    // --- exp (no max subtraction; scores bounded) + block-partial row sums ---
    float prow[4];
#pragma unroll
    for (int r = 0; r < 4; ++r) {
        float ri = rIs[ty + 16 * r];
        float p = 0.f;
#pragma unroll
        for (int s = 0; s < 4; ++s) {
            int j0 = 2 * (tx + 16 * s);
            float e0 = __expf(ri + rJn[j0]     + accf[r][s][0]);
            float e1 = __expf(ri + rJn[j0 + 1] + accf[r][s][1]);
            accf[r][s][0] = e0;
            accf[r][s][1] = e1;
            p += e0 + e1;
        }
        // reduce across the 16 tx lanes (stays within each 16-lane half-warp)
#pragma unroll
        for (int off = 8; off; off >>= 1)
            p += __shfl_xor_sync(0xffffffffu, p, off);
        prow[r] = p;
    }
    if (tx == 0) {
#pragma unroll
        for (int r = 0; r < 4; ++r)
            atomicAdd(&g_rowsum[b * NSEQ + it * 64 + ty + 16 * r], prow[r]);
    }

    // --- rendezvous: wait for all 8 jt-blocks of this (b, it) ---
    __syncthreads();
    if (t == 0) {
        __threadfence();
        unsigned idx = b * 16 + it;
        atomicAdd(&g_cnt[idx], 1u);
        while (atomicAdd(&g_cnt[idx], 0u) < 8u) { }
    }
    __syncthreads();

    if (t < 64) {
        volatile const float* vs = g_rowsum;
        rsum[t] = 1.0f / vs[b * NSEQ + it * 64 + t];
    }
    __syncthreads();

#pragma unroll
    for (int r = 0; r < 4; ++r) {
        int il = ty + 16 * r;
        float inv = rsum[il];
        float* orow = out + ((size_t)(b * NSEQ + it * 64 + il)) * NSEQ + jt * 128;
#pragma unroll
        for (int s = 0; s < 4; ++s) {
            int j0 = 2 * (tx + 16 * s);
            float2 v;
            v.x = accf[r][s][0] * inv;
            v.y = accf[r][s][1] * inv;
            *reinterpret_cast<float2*>(&orow[j0]) = v;
        }
    }
}

// ---------------------------------------------------------------------------
extern "C" void kernel_launch(void* const* d_in, const int* in_sizes, int n_in,
                              void* d_out, int out_size) {
    const float* x  = (const float*)d_in[0];  // [2,1024,64]
    const float* w1 = (const float*)d_in[1];  // [64,64]
    const float* b1 = (const float*)d_in[2];  // [64]
    const float* w2 = (const float*)d_in[3];  // [64]
    const float* b2 = (const float*)d_in[4];  // scalar
    float* out = (float*)d_out;               // [2,1024,1024]

    k1_proj<<<128, 256>>>(x, w1, b1);
    dim3 g2(8, 16, 2);
    k2_scores<<<g2, 256>>>(w2, b2, out);
}